// round 2
// baseline (speedup 1.0000x reference)
#include <cuda_runtime.h>
#include <cuda_bf16.h>
#include <cstdint>

// ---------------- problem constants ----------------
#define E_     13
#define I_     13
#define H_     64
#define G_     256      // 4*H, torch gate order i,f,g,o
#define MT     128      // batch rows per CTA
#define NTILES 24       // 192 gate-cols (i,g,o) / 8
#define THREADS 256     // 8 warps, each owns 16 batch rows

// ---------------- helpers ----------------
static __device__ __forceinline__ uint32_t pack_bf16x2(float lo, float hi) {
    // d.hi = first src, d.lo = second src
    uint32_t r;
    asm("cvt.rn.bf16x2.f32 %0, %1, %2;" : "=r"(r) : "f"(hi), "f"(lo));
    return r;
}
static __device__ __forceinline__ float tanh_a(float v) {
    float y;
    asm("tanh.approx.f32 %0, %1;" : "=f"(y) : "f"(v));
    return y;
}
static __device__ __forceinline__ float sigm_a(float v) {
    return fmaf(tanh_a(v * 0.5f), 0.5f, 0.5f);
}

#define MMA16816(d0,d1,d2,d3, a0,a1,a2,a3, b0,b1)                              \
    asm volatile(                                                              \
        "mma.sync.aligned.m16n8k16.row.col.f32.bf16.bf16.f32 "                 \
        "{%0,%1,%2,%3}, {%4,%5,%6,%7}, {%8,%9}, {%0,%1,%2,%3};"                \
        : "+f"(d0), "+f"(d1), "+f"(d2), "+f"(d3)                               \
        : "r"(a0), "r"(a1), "r"(a2), "r"(a3), "r"(b0), "r"(b1))

// ---------------- kernel ----------------
// Grid (E, B/128). e fastest so the 13 e-CTAs of one b-tile run adjacently
// and L2 merges the stride-52B x reads / out writes.
// CTA: 256 threads = 8 warps; warp w owns batch rows [b0+16w, b0+16w+16).
// Gate matrix N-layout: cols 0-63 = i, 64-127 = g, 128-191 = o (f skipped: f*c0=0).
// K-layout (K=16): k 0-12 = x / W_ih, k 13 = ones-col / (b_ih+b_hh), k 14,15 = 0.
__global__ __launch_bounds__(THREADS) void MusicLSTM_kernel(
    const float* __restrict__ x,      // [B, E, I]
    const float* __restrict__ Wih,    // [E, 4H, I]
    const float* __restrict__ bih,    // [E, 4H]
    const float* __restrict__ bhh,    // [E, 4H]
    const float* __restrict__ Wlin,   // [E, H]
    const float* __restrict__ blin,   // [E]
    float* __restrict__ out)          // [B, E]
{
    __shared__ float    xs[MT * 16];             // [row][k], k padded to 16
    __shared__ uint32_t bfrag[NTILES * 32 * 2];  // prebuilt B fragments per (tile,lane)
    __shared__ float    wl[H_];

    const int tid = threadIdx.x;
    const int e   = blockIdx.x;
    const int b0  = blockIdx.y * MT;

    // ---- stage x into smem ----
    for (int idx = tid; idx < MT * I_; idx += THREADS) {
        int r = idx / I_, c = idx - r * I_;
        xs[r * 16 + c] = x[(size_t)(b0 + r) * (E_ * I_) + e * I_ + c];
    }
    if (tid < MT) {                 // bias ones-column + zero pads
        xs[tid * 16 + 13] = 1.0f;
        xs[tid * 16 + 14] = 0.0f;
        xs[tid * 16 + 15] = 0.0f;
    }
    if (tid < H_) wl[tid] = Wlin[e * H_ + tid];

    // ---- prebuild B fragments (shared by all 8 warps) ----
    // m16n8k16 B layout (col-major KxN): lane = g*4+tg holds
    //   reg0: (k=2tg, 2tg+1 | n=n0+g), reg1: (k=2tg+8, 2tg+9 | n=n0+g)
    for (int p = tid; p < NTILES * 32; p += THREADS) {
        int t  = p >> 5, ln = p & 31;
        int g  = ln >> 2, tg = ln & 3;
        int n  = t * 8 + g;
        int src = (n < 64) ? n : n + 64;          // i:0-63, g:128-191, o:192-255
        const float* wrow = Wih + ((size_t)e * G_ + src) * I_;
        float bsum = bih[e * G_ + src] + bhh[e * G_ + src];
        float v[4];
        const int ks[4] = {2 * tg, 2 * tg + 1, 2 * tg + 8, 2 * tg + 9};
        #pragma unroll
        for (int j = 0; j < 4; j++) {
            int k = ks[j];
            v[j] = (k < I_) ? wrow[k] : ((k == 13) ? bsum : 0.0f);
        }
        bfrag[p * 2 + 0] = pack_bf16x2(v[0], v[1]);
        bfrag[p * 2 + 1] = pack_bf16x2(v[2], v[3]);
    }
    __syncthreads();

    // ---- per-warp MMA + fused epilogue ----
    const int wid = tid >> 5, ln = tid & 31;
    const int g   = ln >> 2,  tg = ln & 3;
    const int r0  = wid * 16;

    // A fragment (single K=16 step, reused across all 24 n-tiles)
    const float* rowA = &xs[(r0 + g) * 16];
    const float* rowB = &xs[(r0 + g + 8) * 16];
    float2 a00 = *(const float2*)(rowA + 2 * tg);
    float2 a10 = *(const float2*)(rowB + 2 * tg);
    float2 a01 = *(const float2*)(rowA + 2 * tg + 8);
    float2 a11 = *(const float2*)(rowB + 2 * tg + 8);
    uint32_t ra0 = pack_bf16x2(a00.x, a00.y);
    uint32_t ra1 = pack_bf16x2(a10.x, a10.y);
    uint32_t ra2 = pack_bf16x2(a01.x, a01.y);
    uint32_t ra3 = pack_bf16x2(a11.x, a11.y);

    float acc0 = 0.0f, acc1 = 0.0f;   // partial W_lin dots for rows g and g+8

    #pragma unroll
    for (int hc = 0; hc < 8; hc++) {
        const uint32_t* bi = &bfrag[(hc)      * 64 + ln * 2];
        const uint32_t* bg = &bfrag[(hc + 8)  * 64 + ln * 2];
        const uint32_t* bo = &bfrag[(hc + 16) * 64 + ln * 2];

        float di0 = 0, di1 = 0, di2 = 0, di3 = 0;
        float dg0 = 0, dg1 = 0, dg2 = 0, dg3 = 0;
        float dq0 = 0, dq1 = 0, dq2 = 0, dq3 = 0;   // o gate
        MMA16816(di0, di1, di2, di3, ra0, ra1, ra2, ra3, bi[0], bi[1]);
        MMA16816(dg0, dg1, dg2, dg3, ra0, ra1, ra2, ra3, bg[0], bg[1]);
        MMA16816(dq0, dq1, dq2, dq3, ra0, ra1, ra2, ra3, bo[0], bo[1]);

        // this thread's h indices in this chunk
        float w0 = wl[hc * 8 + 2 * tg];
        float w1 = wl[hc * 8 + 2 * tg + 1];

        // row g
        {
            float c0 = sigm_a(di0) * tanh_a(dg0);
            float h0 = sigm_a(dq0) * tanh_a(c0);
            acc0 = fmaf(h0, w0, acc0);
            float c1 = sigm_a(di1) * tanh_a(dg1);
            float h1 = sigm_a(dq1) * tanh_a(c1);
            acc0 = fmaf(h1, w1, acc0);
        }
        // row g+8
        {
            float c2 = sigm_a(di2) * tanh_a(dg2);
            float h2 = sigm_a(dq2) * tanh_a(c2);
            acc1 = fmaf(h2, w0, acc1);
            float c3 = sigm_a(di3) * tanh_a(dg3);
            float h3 = sigm_a(dq3) * tanh_a(c3);
            acc1 = fmaf(h3, w1, acc1);
        }
    }

    // reduce across the 4 lanes of each quad (tg bits = lane bits 0,1)
    acc0 += __shfl_xor_sync(0xffffffffu, acc0, 1);
    acc0 += __shfl_xor_sync(0xffffffffu, acc0, 2);
    acc1 += __shfl_xor_sync(0xffffffffu, acc1, 1);
    acc1 += __shfl_xor_sync(0xffffffffu, acc1, 2);

    if (tg == 0) {
        float bl = __ldg(&blin[e]);
        float z0 = acc0 + bl;
        float z1 = acc1 + bl;
        out[(size_t)(b0 + r0 + g)     * E_ + e] = __fdividef(1.0f, 1.0f + __expf(-z0));
        out[(size_t)(b0 + r0 + g + 8) * E_ + e] = __fdividef(1.0f, 1.0f + __expf(-z1));
    }
}

// ---------------- launch ----------------
extern "C" void kernel_launch(void* const* d_in, const int* in_sizes, int n_in,
                              void* d_out, int out_size) {
    const float* x    = (const float*)d_in[0];
    const float* Wih  = (const float*)d_in[1];
    // d_in[2] = W_hh multiplies h0 = 0 -> unused
    const float* bih  = (const float*)d_in[3];
    const float* bhh  = (const float*)d_in[4];
    const float* Wlin = (const float*)d_in[5];
    const float* blin = (const float*)d_in[6];
    float* out = (float*)d_out;

    int Bv = in_sizes[0] / (E_ * I_);    // 131072
    dim3 grid(E_, Bv / MT);              // (13, 1024)
    MusicLSTM_kernel<<<grid, THREADS>>>(x, Wih, bih, bhh, Wlin, blin, out);
}